// round 15
// baseline (speedup 1.0000x reference)
#include <cuda_runtime.h>
#include <cuda_fp16.h>
#include <math.h>
#include <stdint.h>

#define D_MODEL   512
#define D_FF      2048
#define N_EXPERTS 8
#define CAPACITY  10240
#define T_TOKENS  65536
#define NB        64
#define MTILES    (CAPACITY / 128)        // 80

#define OUT_ELEMS   ((long long)T_TOKENS * D_MODEL)
#define ONEHOT_E    ((long long)T_TOKENS * N_EXPERTS)
#define PROBS_E     ((long long)T_TOKENS * N_EXPERTS)

// fp16 GEMM smem: 3-stage ring, block tile 128(M) x 256(N), BK=64.
#define BK        64
#define LDS_H     80
#define STAGE_A_H (128 * LDS_H)
#define STAGE_B_H (256 * LDS_H)
#define NSTAGE    3
#define SMEM_GEMM ((NSTAGE * (STAGE_A_H + STAGE_B_H)) * 2 + 512 + 128)

#define WI_ELEMS  ((long long)N_EXPERTS * D_FF * D_MODEL)
#define WO_ELEMS  ((long long)N_EXPERTS * D_MODEL * D_FF)

#define G1_CTAS   (N_EXPERTS * MTILES * 8)   // 5120? no: 8*80*8 = 5120... (D_FF/256=8 ntiles)
// NOTE: D_FF/256 = 8 n-tiles, so G1 = 8*80*8 = 5120; G2 = 8*80*2 = 1280.
#undef G1_CTAS
#define G1_NT     (D_FF / 256)               // 8
#define G2_NT     (D_MODEL / 256)            // 2
#define G1_CTAS   (N_EXPERTS * MTILES * G1_NT)   // 5120
#define G2_CTAS   (N_EXPERTS * MTILES * G2_NT)   // 1280

// ---------------- scratch ----------------
__device__ float g_probs[T_TOKENS * N_EXPERTS];
__device__ float g_top1[T_TOKENS];
__device__ int   g_expert[T_TOKENS];
__device__ int   g_pos[T_TOKENS];
__device__ int   g_blockCounts[NB * N_EXPERTS];
__device__ int   g_blockOffsets[NB * N_EXPERTS];
__device__ int   g_total[N_EXPERTS];
__device__ float g_pi_sum[N_EXPERTS];
__device__ float g_aux;
__device__ int   g_dropped;
__device__ int   g_slot2tok[N_EXPERTS * CAPACITY];
__device__ int   g_flags[N_EXPERTS * MTILES];
// fp16, k-permuted within 16-groups: p(k) = 4*((k&7)>>1) + (k&1) + 2*(k>>3)
__device__ __half g_xh[(size_t)T_TOKENS * D_MODEL];
__device__ __half g_Wih[(size_t)N_EXPERTS * D_FF * D_MODEL];
__device__ __half g_Woh[(size_t)N_EXPERTS * D_MODEL * D_FF];
__device__ __half g_Hh[(size_t)N_EXPERTS * CAPACITY * D_FF];

// ---------------- helpers ----------------
__device__ __forceinline__ uint32_t s2u(const void* p) {
    uint32_t a;
    asm("{ .reg .u64 t; cvta.to.shared.u64 t, %1; cvt.u32.u64 %0, t; }" : "=r"(a) : "l"(p));
    return a;
}
__device__ __forceinline__ void cpasync16(uint32_t saddr, const void* gaddr) {
    asm volatile("cp.async.cg.shared.global [%0], [%1], 16;" :: "r"(saddr), "l"(gaddr) : "memory");
}
__device__ __forceinline__ void mma16(float* c, uint32_t a0, uint32_t a1, uint32_t a2,
                                      uint32_t a3, uint32_t b0, uint32_t b1) {
    asm volatile(
        "mma.sync.aligned.m16n8k16.row.col.f32.f16.f16.f32 "
        "{%0,%1,%2,%3}, {%4,%5,%6,%7}, {%8,%9}, {%0,%1,%2,%3};"
        : "+f"(c[0]), "+f"(c[1]), "+f"(c[2]), "+f"(c[3])
        : "r"(a0), "r"(a1), "r"(a2), "r"(a3), "r"(b0), "r"(b1));
}
__device__ __forceinline__ int permk16(int k) {
    return 4 * ((k & 7) >> 1) + (k & 1) + 2 * (k >> 3);
}

// ---------------- weight cvt+permute to fp16 (single merged launch) ----------------
__global__ void cvt_perm_w_kernel(const float* __restrict__ wi,
                                  const float* __restrict__ wo) {
    long long g = (long long)blockIdx.x * 256 + threadIdx.x;
    const long long WI_G = WI_ELEMS / 16;
    const float* s;
    __half* dst;
    long long base;
    if (g < WI_G) { s = wi; dst = g_Wih; base = g * 16; }
    else          { s = wo; dst = g_Woh; base = (g - WI_G) * 16; }
    __half out[16];
#pragma unroll
    for (int q = 0; q < 4; q++) {
        float4 v = *(const float4*)(s + base + q * 4);
        float vals[4] = {v.x, v.y, v.z, v.w};
#pragma unroll
        for (int u = 0; u < 4; u++) {
            int k = q * 4 + u;
            out[permk16(k)] = __float2half_rn(vals[u]);
        }
    }
    *(uint4*)(dst + base) = *(uint4*)out;
    *(uint4*)(dst + base + 8) = *(uint4*)(out + 8);
}

// ---------------- routing ----------------
__global__ void zero_kernel() {
    int i = blockIdx.x * 512 + threadIdx.x;
    if (i < N_EXPERTS) g_pi_sum[i] = 0.f;
    if (i < N_EXPERTS * MTILES) g_flags[i] = 0;
}

// One warp per token; fused: router + x->fp16 permuted conversion (L1-hot).
__global__ void router_kernel(const float* __restrict__ x,
                              const float* __restrict__ Wr,
                              const float* __restrict__ br) {
    __shared__ float Ws[N_EXPERTS * D_MODEL];
    __shared__ float brs[N_EXPERTS];
    __shared__ float pis[N_EXPERTS];
    int tid = threadIdx.x;
    for (int i = tid; i < N_EXPERTS * D_MODEL; i += 256) Ws[i] = Wr[i];
    if (tid < N_EXPERTS) { brs[tid] = br[tid]; pis[tid] = 0.f; }
    __syncthreads();

    int warp = tid >> 5, lane = tid & 31;
    int t = blockIdx.x * 8 + warp;

    float acc[N_EXPERTS];
#pragma unroll
    for (int e = 0; e < N_EXPERTS; e++) acc[e] = 0.f;
    const float* xr = x + (size_t)t * D_MODEL;
#pragma unroll
    for (int i = 0; i < D_MODEL / 32; i++) {
        int c = lane + i * 32;
        float v = xr[c];
#pragma unroll
        for (int e = 0; e < N_EXPERTS; e++) acc[e] += v * Ws[e * D_MODEL + c];
    }

    {
        __half out[16];
        const float4* xq = (const float4*)xr + lane * 4;
#pragma unroll
        for (int q = 0; q < 4; q++) {
            float4 v = xq[q];
            float vals[4] = {v.x, v.y, v.z, v.w};
#pragma unroll
            for (int u = 0; u < 4; u++) {
                int k = q * 4 + u;
                out[permk16(k)] = __float2half_rn(vals[u]);
            }
        }
        uint4* dst = (uint4*)(g_xh + (size_t)t * D_MODEL + lane * 16);
        dst[0] = *(uint4*)out;
        dst[1] = *(uint4*)(out + 8);
    }

#pragma unroll
    for (int e = 0; e < N_EXPERTS; e++) {
#pragma unroll
        for (int off = 16; off > 0; off >>= 1)
            acc[e] += __shfl_down_sync(0xffffffffu, acc[e], off);
    }
    if (lane == 0) {
        float l[N_EXPERTS];
        float mx = -INFINITY; int idx = 0;
#pragma unroll
        for (int e = 0; e < N_EXPERTS; e++) {
            l[e] = acc[e] + brs[e];
            if (l[e] > mx) { mx = l[e]; idx = e; }
        }
        float s = 0.f, pr[N_EXPERTS];
#pragma unroll
        for (int e = 0; e < N_EXPERTS; e++) { pr[e] = expf(l[e] - mx); s += pr[e]; }
        float inv = 1.f / s;
#pragma unroll
        for (int e = 0; e < N_EXPERTS; e++) {
            float p = pr[e] * inv;
            g_probs[(size_t)t * N_EXPERTS + e] = p;
            atomicAdd(&pis[e], p);
        }
        g_top1[t] = pr[idx] * inv;
        g_expert[t] = idx;
    }
    __syncthreads();
    if (tid < N_EXPERTS) atomicAdd(&g_pi_sum[tid], pis[tid]);
}

__global__ void count_kernel() {
    __shared__ int c[N_EXPERTS];
    if (threadIdx.x < N_EXPERTS) c[threadIdx.x] = 0;
    __syncthreads();
    int t = blockIdx.x * 1024 + threadIdx.x;
    atomicAdd(&c[g_expert[t]], 1);
    __syncthreads();
    if (threadIdx.x < N_EXPERTS)
        g_blockCounts[blockIdx.x * N_EXPERTS + threadIdx.x] = c[threadIdx.x];
}

__global__ void scan_kernel() {
    __shared__ int warpTot[16];
    __shared__ int tot[N_EXPERTS];
    int tid = threadIdx.x;
    int e = tid >> 6, b = tid & 63;
    int w = tid >> 5, lane = tid & 31;
    int v = g_blockCounts[b * N_EXPERTS + e];
    int incl = v;
#pragma unroll
    for (int off = 1; off < 32; off <<= 1) {
        int n = __shfl_up_sync(0xffffffffu, incl, off);
        if (lane >= off) incl += n;
    }
    if (lane == 31) warpTot[w] = incl;
    __syncthreads();
    if (b >= 32) incl += warpTot[w - 1];
    g_blockOffsets[b * N_EXPERTS + e] = incl - v;
    if (b == 63) tot[e] = incl;
    __syncthreads();
    if (tid < N_EXPERTS) g_total[tid] = tot[tid];
    if (tid == 0) {
        float aux = 0.f; int drop = 0;
        for (int k = 0; k < N_EXPERTS; k++) {
            int tt = tot[k];
            int kept = tt < CAPACITY ? tt : CAPACITY;
            drop += tt - kept;
            float fi = (float)kept / (float)T_TOKENS;
            float pi = g_pi_sum[k] / (float)T_TOKENS;
            aux += fi * pi;
        }
        g_aux = aux * (float)N_EXPERTS;
        g_dropped = drop;
    }
}

__global__ void rank_kernel() {
    __shared__ int warpCnt[32][N_EXPERTS];
    __shared__ int warpOff[32][N_EXPERTS];
    int tid = threadIdx.x, w = tid >> 5, lane = tid & 31;
    int t = blockIdx.x * 1024 + tid;
    int e = g_expert[t];
    unsigned lt = (lane == 0) ? 0u : (0xffffffffu >> (32 - lane));
    int myrank = 0;
#pragma unroll
    for (int k = 0; k < N_EXPERTS; k++) {
        unsigned m = __ballot_sync(0xffffffffu, e == k);
        if (lane == 0) warpCnt[w][k] = __popc(m);
        if (e == k) myrank = __popc(m & lt);
    }
    __syncthreads();
    if (tid < 32 * N_EXPERTS) {
        int ww = tid >> 3, k = tid & 7;
        int s = 0;
        for (int u = 0; u < ww; u++) s += warpCnt[u][k];
        warpOff[ww][k] = s;
    }
    __syncthreads();
    int pos = g_blockOffsets[blockIdx.x * N_EXPERTS + e] + warpOff[w][e] + myrank;
    g_pos[t] = pos;
    if (pos < CAPACITY) g_slot2tok[e * CAPACITY + pos] = t;
}

// ---------------- fp16 mma.sync GEMM tile (R11 mainloop, best measured) ----------------
template<int K_TOT, bool GATHER, bool RELU>
__device__ __forceinline__ void gemm_tile(__half* smemh, int e, int mt, int n0,
                                          float* __restrict__ Dglob) {
    __half* sA = smemh;
    __half* sB = smemh + NSTAGE * STAGE_A_H;
    int* tokS = (int*)(smemh + NSTAGE * (STAGE_A_H + STAGE_B_H));

    int ne = g_total[e]; if (ne > CAPACITY) ne = CAPACITY;
    int m0 = mt * 128;
    if (m0 >= ne) return;

    int tid = threadIdx.x;
    int wid = tid >> 5, lane = tid & 31;
    int wm = wid >> 2, wn = wid & 3;
    int qr = lane >> 2, j = lane & 3;

    // GEMM2: wait until all 8 GEMM1 n-tiles for (e, mt) have committed H.
    if (!RELU) {
        if (tid == 0) {
            while (atomicAdd(&g_flags[e * MTILES + mt], 0) < G1_NT) __nanosleep(200);
        }
        __syncthreads();
        __threadfence();
    }

    if (GATHER && tid < 128) {
        int m = m0 + tid;
        tokS[tid] = (m < ne) ? g_slot2tok[e * CAPACITY + m] : 0;
    }
    __syncthreads();

    const __half* Bbase = (RELU ? g_Wih : g_Woh) +
        ((size_t)e * (RELU ? D_FF : D_MODEL) + n0) * K_TOT;
    const __half* Hbase = g_Hh + ((size_t)e * CAPACITY + m0) * (size_t)D_FF;

    int lrowA = tid >> 2, lqA = tid & 3;
    const __half* aRowPtr;
    if (GATHER) aRowPtr = g_xh + (size_t)tokS[lrowA] * D_MODEL + lqA * 16;
    else        aRowPtr = Hbase + (size_t)lrowA * D_FF + lqA * 16;
    uint32_t sAu = s2u(sA) + (lrowA * LDS_H + lqA * 16) * 2;
    int lrowB = tid >> 1, lqB = tid & 1;
    const __half* bRowPtr = Bbase + (size_t)lrowB * K_TOT + lqB * 32;
    uint32_t sBu = s2u(sB) + (lrowB * LDS_H + lqB * 32) * 2;

    float acc[2][8][4];
#pragma unroll
    for (int mi = 0; mi < 2; mi++)
#pragma unroll
        for (int ni = 0; ni < 8; ni++)
#pragma unroll
            for (int r = 0; r < 4; r++) acc[mi][ni][r] = 0.f;

    const int NS = K_TOT / BK;
#pragma unroll
    for (int s = 0; s < 2; s++) {
        uint32_t soA = s * STAGE_A_H * 2;
        uint32_t soB = s * STAGE_B_H * 2;
        const __half* ap = aRowPtr + s * BK;
        const __half* bp = bRowPtr + s * BK;
        cpasync16(sAu + soA,      ap);
        cpasync16(sAu + soA + 16, ap + 8);
        cpasync16(sBu + soB,      bp);
        cpasync16(sBu + soB + 16, bp + 8);
        cpasync16(sBu + soB + 32, bp + 16);
        cpasync16(sBu + soB + 48, bp + 24);
        asm volatile("cp.async.commit_group;" ::: "memory");
    }

    int cur = 0, pre = 2;
    for (int s = 0; s < NS; s++) {
        asm volatile("cp.async.wait_group 1;" ::: "memory");
        __syncthreads();
        if (s + 2 < NS) {
            uint32_t soA = pre * STAGE_A_H * 2;
            uint32_t soB = pre * STAGE_B_H * 2;
            const __half* ap = aRowPtr + (s + 2) * BK;
            const __half* bp = bRowPtr + (s + 2) * BK;
            cpasync16(sAu + soA,      ap);
            cpasync16(sAu + soA + 16, ap + 8);
            cpasync16(sBu + soB,      bp);
            cpasync16(sBu + soB + 16, bp + 8);
            cpasync16(sBu + soB + 32, bp + 16);
            cpasync16(sBu + soB + 48, bp + 24);
        }
        asm volatile("cp.async.commit_group;" ::: "memory");

        const __half* A = sA + cur * STAGE_A_H;
        const __half* B = sB + cur * STAGE_B_H;

#pragma unroll
        for (int kc = 0; kc < 4; kc++) {
            int co = kc * 16 + j * 4;
            uint2 af[2][2], bf[8];
#pragma unroll
            for (int mi = 0; mi < 2; mi++) {
                int r = wm * 32 + mi * 16 + qr;
                af[mi][0] = *(const uint2*)&A[r * LDS_H + co];
                af[mi][1] = *(const uint2*)&A[(r + 8) * LDS_H + co];
            }
#pragma unroll
            for (int ni = 0; ni < 8; ni++) {
                int r = wn * 64 + ni * 8 + qr;
                bf[ni] = *(const uint2*)&B[r * LDS_H + co];
            }
#pragma unroll
            for (int mi = 0; mi < 2; mi++)
#pragma unroll
                for (int ni = 0; ni < 8; ni++)
                    mma16(acc[mi][ni],
                          af[mi][0].x, af[mi][1].x, af[mi][0].y, af[mi][1].y,
                          bf[ni].x, bf[ni].y);
        }
        cur++; if (cur == NSTAGE) cur = 0;
        pre++; if (pre == NSTAGE) pre = 0;
    }

    // epilogue
#pragma unroll
    for (int mi = 0; mi < 2; mi++) {
#pragma unroll
        for (int half = 0; half < 2; half++) {
            int m = m0 + wm * 32 + mi * 16 + qr + half * 8;
            if (m >= ne) continue;
            if (RELU) {
                __half* rowptr = g_Hh + ((size_t)e * CAPACITY + m) * D_FF + n0;
#pragma unroll
                for (int ni = 0; ni < 8; ni++) {
                    float v0 = fmaxf(acc[mi][ni][half * 2 + 0], 0.f);
                    float v1 = fmaxf(acc[mi][ni][half * 2 + 1], 0.f);
                    int c = wn * 64 + ni * 8 + 2 * j;
                    int base16 = c & ~15;
                    int cm = c & 15;
                    int off = 4 * ((cm & 7) >> 1) + 2 * (cm >> 3);
                    __half2 hv = __floats2half2_rn(v0, v1);
                    *(__half2*)(rowptr + base16 + off) = hv;
                }
            } else {
                int tk = g_slot2tok[e * CAPACITY + m];
                float sc = g_top1[tk];
                float* rowptr = Dglob + (size_t)tk * D_MODEL + n0;
#pragma unroll
                for (int ni = 0; ni < 8; ni++) {
                    int c = wn * 64 + ni * 8 + 2 * j;
                    float2 v;
                    v.x = acc[mi][ni][half * 2 + 0] * sc;
                    v.y = acc[mi][ni][half * 2 + 1] * sc;
                    *(float2*)(rowptr + c) = v;
                }
            }
        }
    }

    // GEMM1: commit H tile -> bump group flag.
    if (RELU) {
        __threadfence();
        __syncthreads();
        if (tid == 0) atomicAdd(&g_flags[e * MTILES + mt], 1);
    }
}

// Fused launch: bids [0, G1_CTAS) = GEMM1, [G1_CTAS, G1_CTAS+G2_CTAS) = GEMM2.
__global__ void __launch_bounds__(512, 1)
fused_gemm(float* __restrict__ outp) {
    extern __shared__ __half smemh[];
    int bid = blockIdx.x;
    if (bid < G1_CTAS) {
        int e = bid / (MTILES * G1_NT);
        int r = bid % (MTILES * G1_NT);
        int mt = r / G1_NT, nt = r % G1_NT;
        gemm_tile<D_MODEL, true, true>(smemh, e, mt, nt * 256, nullptr);
    } else {
        int r = bid - G1_CTAS;
        int e = r / (MTILES * G2_NT);
        int q = r % (MTILES * G2_NT);
        int mt = q / G2_NT, nt = q % G2_NT;
        gemm_tile<D_FF, false, false>(smemh, e, mt, nt * 256, outp);
    }
}

__global__ void drop_kernel(float* __restrict__ outp) {
    for (int t = blockIdx.x * blockDim.x + threadIdx.x; t < T_TOKENS;
         t += gridDim.x * blockDim.x) {
        if (g_pos[t] >= CAPACITY) {
            float4 z = make_float4(0.f, 0.f, 0.f, 0.f);
            float4* p = (float4*)(outp + (size_t)t * D_MODEL);
            for (int i = 0; i < D_MODEL / 4; i++) p[i] = z;
        }
    }
}

__global__ void extras_kernel(float* __restrict__ outp, long long out_size) {
    long long i = (long long)blockIdx.x * blockDim.x + threadIdx.x;
    long long off = OUT_ELEMS + i;
    if (off >= out_size) return;
    long long r = i;
    if (r < ONEHOT_E) {
        int t = (int)(r >> 3), e = (int)(r & 7);
        outp[off] = (g_expert[t] == e && g_pos[t] < CAPACITY) ? 1.f : 0.f;
        return;
    }
    r -= ONEHOT_E;
    if (r < T_TOKENS) { outp[off] = g_top1[r]; return; }
    r -= T_TOKENS;
    if (r < PROBS_E) { outp[off] = g_probs[r]; return; }
    r -= PROBS_E;
    if (r == 0) { outp[off] = g_aux; return; }
    outp[off] = (float)g_dropped;
}

// ---------------- launch ----------------
extern "C" void kernel_launch(void* const* d_in, const int* in_sizes, int n_in,
                              void* d_out, int out_size) {
    const float* x  = (const float*)d_in[0];
    const float* Wr = (const float*)d_in[1];
    const float* br = (const float*)d_in[2];
    const float* Wi = (const float*)d_in[3];
    const float* Wo = (const float*)d_in[4];
    float* outp = (float*)d_out;

    cudaFuncSetAttribute(fused_gemm,
                         cudaFuncAttributeMaxDynamicSharedMemorySize, SMEM_GEMM);

    zero_kernel<<<2, 512>>>();
    router_kernel<<<T_TOKENS / 8, 256>>>(x, Wr, br);
    count_kernel<<<NB, 1024>>>();
    scan_kernel<<<1, 512>>>();
    rank_kernel<<<NB, 1024>>>();

    cvt_perm_w_kernel<<<(unsigned)(((WI_ELEMS + WO_ELEMS) / 16) / 256), 256>>>(Wi, Wo);

    fused_gemm<<<G1_CTAS + G2_CTAS, 512, SMEM_GEMM>>>(outp);

    drop_kernel<<<256, 256>>>(outp);

    long long extra = (long long)out_size - OUT_ELEMS;
    if (extra > 0) {
        unsigned nb = (unsigned)((extra + 255) / 256);
        extras_kernel<<<nb, 256>>>(outp, (long long)out_size);
    }
}

// round 16
// speedup vs baseline: 1.0159x; 1.0159x over previous
#include <cuda_runtime.h>
#include <cuda_fp16.h>
#include <math.h>
#include <stdint.h>

#define D_MODEL   512
#define D_FF      2048
#define N_EXPERTS 8
#define CAPACITY  10240
#define T_TOKENS  65536
#define NB        64

#define OUT_ELEMS   ((long long)T_TOKENS * D_MODEL)
#define ONEHOT_E    ((long long)T_TOKENS * N_EXPERTS)
#define PROBS_E    ((long long)T_TOKENS * N_EXPERTS)

// fp16 GEMM smem: 3-stage ring, block tile 128(M) x 256(N), BK=64.
#define BK        64
#define LDS_H     80
#define STAGE_A_H (128 * LDS_H)          // 10240 halves
#define STAGE_B_H (256 * LDS_H)          // 20480 halves
#define NSTAGE    3
#define SMEM_GEMM ((NSTAGE * (STAGE_A_H + STAGE_B_H)) * 2 + 512 + 128)  // ~185 KB

#define WI_ELEMS  ((long long)N_EXPERTS * D_FF * D_MODEL)
#define WO_ELEMS  ((long long)N_EXPERTS * D_MODEL * D_FF)

// ---------------- scratch ----------------
__device__ float g_probs[T_TOKENS * N_EXPERTS];
__device__ float g_top1[T_TOKENS];
__device__ int   g_expert[T_TOKENS];
__device__ int   g_pos[T_TOKENS];
__device__ int   g_blockCounts[NB * N_EXPERTS];
__device__ int   g_blockOffsets[NB * N_EXPERTS];
__device__ int   g_total[N_EXPERTS];
__device__ float g_pi_sum[N_EXPERTS];
__device__ float g_aux;
__device__ int   g_dropped;
__device__ int   g_slot2tok[N_EXPERTS * CAPACITY];
// fp16, k-permuted within 16-groups: p(k) = 4*((k&7)>>1) + (k&1) + 2*(k>>3)
__device__ __half g_xh[(size_t)T_TOKENS * D_MODEL];
__device__ __half g_Wih[(size_t)N_EXPERTS * D_FF * D_MODEL];
__device__ __half g_Woh[(size_t)N_EXPERTS * D_MODEL * D_FF];
__device__ __half g_Hh[(size_t)N_EXPERTS * CAPACITY * D_FF];

// ---------------- helpers ----------------
__device__ __forceinline__ uint32_t s2u(const void* p) {
    uint32_t a;
    asm("{ .reg .u64 t; cvta.to.shared.u64 t, %1; cvt.u32.u64 %0, t; }" : "=r"(a) : "l"(p));
    return a;
}
__device__ __forceinline__ void cpasync16(uint32_t saddr, const void* gaddr) {
    asm volatile("cp.async.cg.shared.global [%0], [%1], 16;" :: "r"(saddr), "l"(gaddr) : "memory");
}
__device__ __forceinline__ void mma16(float* c, uint32_t a0, uint32_t a1, uint32_t a2,
                                      uint32_t a3, uint32_t b0, uint32_t b1) {
    asm volatile(
        "mma.sync.aligned.m16n8k16.row.col.f32.f16.f16.f32 "
        "{%0,%1,%2,%3}, {%4,%5,%6,%7}, {%8,%9}, {%0,%1,%2,%3};"
        : "+f"(c[0]), "+f"(c[1]), "+f"(c[2]), "+f"(c[3])
        : "r"(a0), "r"(a1), "r"(a2), "r"(a3), "r"(b0), "r"(b1));
}
__device__ __forceinline__ int permk16(int k) {
    return 4 * ((k & 7) >> 1) + (k & 1) + 2 * (k >> 3);
}

// ---------------- weight cvt+permute to fp16 (single merged launch) ----------------
__global__ void cvt_perm_w_kernel(const float* __restrict__ wi,
                                  const float* __restrict__ wo) {
    long long g = (long long)blockIdx.x * 256 + threadIdx.x;
    const long long WI_G = WI_ELEMS / 16;
    const float* s;
    __half* dst;
    long long base;
    if (g < WI_G) { s = wi; dst = g_Wih; base = g * 16; }
    else          { s = wo; dst = g_Woh; base = (g - WI_G) * 16; }
    __half out[16];
#pragma unroll
    for (int q = 0; q < 4; q++) {
        float4 v = *(const float4*)(s + base + q * 4);
        float vals[4] = {v.x, v.y, v.z, v.w};
#pragma unroll
        for (int u = 0; u < 4; u++) {
            int k = q * 4 + u;
            out[permk16(k)] = __float2half_rn(vals[u]);
        }
    }
    *(uint4*)(dst + base) = *(uint4*)out;
    *(uint4*)(dst + base + 8) = *(uint4*)(out + 8);
}

// ---------------- routing ----------------
__global__ void zero_kernel() {
    int i = blockIdx.x * 512 + threadIdx.x;
    if (i < N_EXPERTS) g_pi_sum[i] = 0.f;
    if (i < NB * N_EXPERTS) g_blockCounts[i] = 0;
}

// One warp per token; fused: router + x->fp16 permuted conversion (L1-hot)
// + per-1024-token-block expert counting (replaces count_kernel).
__global__ void router_kernel(const float* __restrict__ x,
                              const float* __restrict__ Wr,
                              const float* __restrict__ br) {
    __shared__ float Ws[N_EXPERTS * D_MODEL];
    __shared__ float brs[N_EXPERTS];
    __shared__ float pis[N_EXPERTS];
    int tid = threadIdx.x;
    for (int i = tid; i < N_EXPERTS * D_MODEL; i += 256) Ws[i] = Wr[i];
    if (tid < N_EXPERTS) { brs[tid] = br[tid]; pis[tid] = 0.f; }
    __syncthreads();

    int warp = tid >> 5, lane = tid & 31;
    int t = blockIdx.x * 8 + warp;

    float acc[N_EXPERTS];
#pragma unroll
    for (int e = 0; e < N_EXPERTS; e++) acc[e] = 0.f;
    const float* xr = x + (size_t)t * D_MODEL;
#pragma unroll
    for (int i = 0; i < D_MODEL / 32; i++) {
        int c = lane + i * 32;
        float v = xr[c];
#pragma unroll
        for (int e = 0; e < N_EXPERTS; e++) acc[e] += v * Ws[e * D_MODEL + c];
    }

    {
        __half out[16];
        const float4* xq = (const float4*)xr + lane * 4;
#pragma unroll
        for (int q = 0; q < 4; q++) {
            float4 v = xq[q];
            float vals[4] = {v.x, v.y, v.z, v.w};
#pragma unroll
            for (int u = 0; u < 4; u++) {
                int k = q * 4 + u;
                out[permk16(k)] = __float2half_rn(vals[u]);
            }
        }
        uint4* dst = (uint4*)(g_xh + (size_t)t * D_MODEL + lane * 16);
        dst[0] = *(uint4*)out;
        dst[1] = *(uint4*)(out + 8);
    }

#pragma unroll
    for (int e = 0; e < N_EXPERTS; e++) {
#pragma unroll
        for (int off = 16; off > 0; off >>= 1)
            acc[e] += __shfl_down_sync(0xffffffffu, acc[e], off);
    }
    if (lane == 0) {
        float l[N_EXPERTS];
        float mx = -INFINITY; int idx = 0;
#pragma unroll
        for (int e = 0; e < N_EXPERTS; e++) {
            l[e] = acc[e] + brs[e];
            if (l[e] > mx) { mx = l[e]; idx = e; }
        }
        float s = 0.f, pr[N_EXPERTS];
#pragma unroll
        for (int e = 0; e < N_EXPERTS; e++) { pr[e] = expf(l[e] - mx); s += pr[e]; }
        float inv = 1.f / s;
#pragma unroll
        for (int e = 0; e < N_EXPERTS; e++) {
            float p = pr[e] * inv;
            g_probs[(size_t)t * N_EXPERTS + e] = p;
            atomicAdd(&pis[e], p);
        }
        g_top1[t] = pr[idx] * inv;
        g_expert[t] = idx;
        atomicAdd(&g_blockCounts[(t >> 10) * N_EXPERTS + idx], 1);
    }
    __syncthreads();
    if (tid < N_EXPERTS) atomicAdd(&g_pi_sum[tid], pis[tid]);
}

__global__ void scan_kernel() {
    __shared__ int warpTot[16];
    __shared__ int tot[N_EXPERTS];
    int tid = threadIdx.x;
    int e = tid >> 6, b = tid & 63;
    int w = tid >> 5, lane = tid & 31;
    int v = g_blockCounts[b * N_EXPERTS + e];
    int incl = v;
#pragma unroll
    for (int off = 1; off < 32; off <<= 1) {
        int n = __shfl_up_sync(0xffffffffu, incl, off);
        if (lane >= off) incl += n;
    }
    if (lane == 31) warpTot[w] = incl;
    __syncthreads();
    if (b >= 32) incl += warpTot[w - 1];
    g_blockOffsets[b * N_EXPERTS + e] = incl - v;
    if (b == 63) tot[e] = incl;
    __syncthreads();
    if (tid < N_EXPERTS) g_total[tid] = tot[tid];
    if (tid == 0) {
        float aux = 0.f; int drop = 0;
        for (int k = 0; k < N_EXPERTS; k++) {
            int tt = tot[k];
            int kept = tt < CAPACITY ? tt : CAPACITY;
            drop += tt - kept;
            float fi = (float)kept / (float)T_TOKENS;
            float pi = g_pi_sum[k] / (float)T_TOKENS;
            aux += fi * pi;
        }
        g_aux = aux * (float)N_EXPERTS;
        g_dropped = drop;
    }
}

__global__ void rank_kernel() {
    __shared__ int warpCnt[32][N_EXPERTS];
    __shared__ int warpOff[32][N_EXPERTS];
    int tid = threadIdx.x, w = tid >> 5, lane = tid & 31;
    int t = blockIdx.x * 1024 + tid;
    int e = g_expert[t];
    unsigned lt = (lane == 0) ? 0u : (0xffffffffu >> (32 - lane));
    int myrank = 0;
#pragma unroll
    for (int k = 0; k < N_EXPERTS; k++) {
        unsigned m = __ballot_sync(0xffffffffu, e == k);
        if (lane == 0) warpCnt[w][k] = __popc(m);
        if (e == k) myrank = __popc(m & lt);
    }
    __syncthreads();
    if (tid < 32 * N_EXPERTS) {
        int ww = tid >> 3, k = tid & 7;
        int s = 0;
        for (int u = 0; u < ww; u++) s += warpCnt[u][k];
        warpOff[ww][k] = s;
    }
    __syncthreads();
    int pos = g_blockOffsets[blockIdx.x * N_EXPERTS + e] + warpOff[w][e] + myrank;
    g_pos[t] = pos;
    if (pos < CAPACITY) g_slot2tok[e * CAPACITY + pos] = t;
}

// ---------------- fp16 mma.sync GEMM, 128x256 tile, BK=64, 3-stage ----------------
// warp tile 32(M) x 64(N); 4x4 warps.  (R11 mainloop — best measured.)
template<int K_TOT, bool GATHER, bool RELU>
__global__ void __launch_bounds__(512, 1)
gemm_mma(float* __restrict__ Dglob) {
    extern __shared__ __half smemh[];
    __half* sA = smemh;                                  // 3 x 128x80
    __half* sB = smemh + NSTAGE * STAGE_A_H;             // 3 x 256x80
    int* tokS = (int*)(smemh + NSTAGE * (STAGE_A_H + STAGE_B_H));

    int e = blockIdx.z;
    int ne = g_total[e]; if (ne > CAPACITY) ne = CAPACITY;
    int m0 = blockIdx.y * 128;
    if (m0 >= ne) return;
    int n0 = blockIdx.x * 256;

    int tid = threadIdx.x;
    int wid = tid >> 5, lane = tid & 31;
    int wm = wid >> 2, wn = wid & 3;
    int qr = lane >> 2, j = lane & 3;

    if (GATHER && tid < 128) {
        int m = m0 + tid;
        tokS[tid] = (m < ne) ? g_slot2tok[e * CAPACITY + m] : 0;
    }
    __syncthreads();

    const __half* Bbase = (RELU ? g_Wih : g_Woh) +
        ((size_t)e * (RELU ? D_FF : D_MODEL) + n0) * K_TOT;
    const __half* Hbase = g_Hh + ((size_t)e * CAPACITY + m0) * (size_t)D_FF;

    // A loader: 4 threads/row, 16 halves (2 x cp16) each
    int lrowA = tid >> 2, lqA = tid & 3;
    const __half* aRowPtr;
    if (GATHER) aRowPtr = g_xh + (size_t)tokS[lrowA] * D_MODEL + lqA * 16;
    else        aRowPtr = Hbase + (size_t)lrowA * D_FF + lqA * 16;
    uint32_t sAu = s2u(sA) + (lrowA * LDS_H + lqA * 16) * 2;
    // B loader: 2 threads/row, 32 halves (4 x cp16) each
    int lrowB = tid >> 1, lqB = tid & 1;
    const __half* bRowPtr = Bbase + (size_t)lrowB * K_TOT + lqB * 32;
    uint32_t sBu = s2u(sB) + (lrowB * LDS_H + lqB * 32) * 2;

    float acc[2][8][4];
#pragma unroll
    for (int mi = 0; mi < 2; mi++)
#pragma unroll
        for (int ni = 0; ni < 8; ni++)
#pragma unroll
            for (int r = 0; r < 4; r++) acc[mi][ni][r] = 0.f;

    const int NS = K_TOT / BK;
    // prologue: 2 stages in flight
#pragma unroll
    for (int s = 0; s < 2; s++) {
        uint32_t soA = s * STAGE_A_H * 2;
        uint32_t soB = s * STAGE_B_H * 2;
        const __half* ap = aRowPtr + s * BK;
        const __half* bp = bRowPtr + s * BK;
        cpasync16(sAu + soA,      ap);
        cpasync16(sAu + soA + 16, ap + 8);
        cpasync16(sBu + soB,      bp);
        cpasync16(sBu + soB + 16, bp + 8);
        cpasync16(sBu + soB + 32, bp + 16);
        cpasync16(sBu + soB + 48, bp + 24);
        asm volatile("cp.async.commit_group;" ::: "memory");
    }

    int cur = 0, pre = 2;
    for (int s = 0; s < NS; s++) {
        asm volatile("cp.async.wait_group 1;" ::: "memory");
        __syncthreads();
        if (s + 2 < NS) {
            uint32_t soA = pre * STAGE_A_H * 2;
            uint32_t soB = pre * STAGE_B_H * 2;
            const __half* ap = aRowPtr + (s + 2) * BK;
            const __half* bp = bRowPtr + (s + 2) * BK;
            cpasync16(sAu + soA,      ap);
            cpasync16(sAu + soA + 16, ap + 8);
            cpasync16(sBu + soB,      bp);
            cpasync16(sBu + soB + 16, bp + 8);
            cpasync16(sBu + soB + 32, bp + 16);
            cpasync16(sBu + soB + 48, bp + 24);
        }
        asm volatile("cp.async.commit_group;" ::: "memory");

        const __half* A = sA + cur * STAGE_A_H;
        const __half* B = sB + cur * STAGE_B_H;

#pragma unroll
        for (int kc = 0; kc < 4; kc++) {
            int co = kc * 16 + j * 4;
            uint2 af[2][2], bf[8];
#pragma unroll
            for (int mi = 0; mi < 2; mi++) {
                int r = wm * 32 + mi * 16 + qr;
                af[mi][0] = *(const uint2*)&A[r * LDS_H + co];
                af[mi][1] = *(const uint2*)&A[(r + 8) * LDS_H + co];
            }
#pragma unroll
            for (int ni = 0; ni < 8; ni++) {
                int r = wn * 64 + ni * 8 + qr;
                bf[ni] = *(const uint2*)&B[r * LDS_H + co];
            }
#pragma unroll
            for (int mi = 0; mi < 2; mi++)
#pragma unroll
                for (int ni = 0; ni < 8; ni++)
                    mma16(acc[mi][ni],
                          af[mi][0].x, af[mi][1].x, af[mi][0].y, af[mi][1].y,
                          bf[ni].x, bf[ni].y);
        }
        cur++; if (cur == NSTAGE) cur = 0;
        pre++; if (pre == NSTAGE) pre = 0;
    }

    // epilogue
#pragma unroll
    for (int mi = 0; mi < 2; mi++) {
#pragma unroll
        for (int half = 0; half < 2; half++) {
            int m = m0 + wm * 32 + mi * 16 + qr + half * 8;
            if (m >= ne) continue;
            if (RELU) {
                __half* rowptr = g_Hh + ((size_t)e * CAPACITY + m) * D_FF + n0;
#pragma unroll
                for (int ni = 0; ni < 8; ni++) {
                    float v0 = fmaxf(acc[mi][ni][half * 2 + 0], 0.f);
                    float v1 = fmaxf(acc[mi][ni][half * 2 + 1], 0.f);
                    int c = wn * 64 + ni * 8 + 2 * j;
                    int base16 = c & ~15;
                    int cm = c & 15;
                    int off = 4 * ((cm & 7) >> 1) + 2 * (cm >> 3);
                    __half2 hv = __floats2half2_rn(v0, v1);
                    *(__half2*)(rowptr + base16 + off) = hv;
                }
            } else {
                int tk = g_slot2tok[e * CAPACITY + m];
                float sc = g_top1[tk];
                float* rowptr = Dglob + (size_t)tk * D_MODEL + n0;
#pragma unroll
                for (int ni = 0; ni < 8; ni++) {
                    int c = wn * 64 + ni * 8 + 2 * j;
                    float2 v;
                    v.x = acc[mi][ni][half * 2 + 0] * sc;
                    v.y = acc[mi][ni][half * 2 + 1] * sc;
                    *(float2*)(rowptr + c) = v;
                }
            }
        }
    }
}

// Merged: zero dropped-token rows + fill extras tail (if out_size demands it).
__global__ void finish_kernel(float* __restrict__ outp, long long out_size) {
    long long i = (long long)blockIdx.x * blockDim.x + threadIdx.x;
    if (i < T_TOKENS) {
        int t = (int)i;
        if (g_pos[t] >= CAPACITY) {
            float4 z = make_float4(0.f, 0.f, 0.f, 0.f);
            float4* p = (float4*)(outp + (size_t)t * D_MODEL);
#pragma unroll 4
            for (int q = 0; q < D_MODEL / 4; q++) p[q] = z;
        }
        return;
    }
    long long r = i - T_TOKENS;
    long long off = OUT_ELEMS + r;
    if (off >= out_size) return;
    if (r < ONEHOT_E) {
        int t = (int)(r >> 3), e = (int)(r & 7);
        outp[off] = (g_expert[t] == e && g_pos[t] < CAPACITY) ? 1.f : 0.f;
        return;
    }
    r -= ONEHOT_E;
    if (r < T_TOKENS) { outp[off] = g_top1[r]; return; }
    r -= T_TOKENS;
    if (r < PROBS_E) { outp[off] = g_probs[r]; return; }
    r -= PROBS_E;
    if (r == 0) { outp[off] = g_aux; return; }
    outp[off] = (float)g_dropped;
}

// ---------------- launch ----------------
extern "C" void kernel_launch(void* const* d_in, const int* in_sizes, int n_in,
                              void* d_out, int out_size) {
    const float* x  = (const float*)d_in[0];
    const float* Wr = (const float*)d_in[1];
    const float* br = (const float*)d_in[2];
    const float* Wi = (const float*)d_in[3];
    const float* Wo = (const float*)d_in[4];
    float* outp = (float*)d_out;

    cudaFuncSetAttribute(gemm_mma<D_MODEL, true, true>,
                         cudaFuncAttributeMaxDynamicSharedMemorySize, SMEM_GEMM);
    cudaFuncSetAttribute(gemm_mma<D_FF, false, false>,
                         cudaFuncAttributeMaxDynamicSharedMemorySize, SMEM_GEMM);

    zero_kernel<<<1, 512>>>();
    router_kernel<<<T_TOKENS / 8, 256>>>(x, Wr, br);
    scan_kernel<<<1, 512>>>();
    rank_kernel<<<NB, 1024>>>();

    cvt_perm_w_kernel<<<(unsigned)(((WI_ELEMS + WO_ELEMS) / 16) / 256), 256>>>(Wi, Wo);

    dim3 g1(D_FF / 256, CAPACITY / 128, N_EXPERTS);
    gemm_mma<D_MODEL, true, true><<<g1, 512, SMEM_GEMM>>>(nullptr);
    dim3 g2(D_MODEL / 256, CAPACITY / 128, N_EXPERTS);
    gemm_mma<D_FF, false, false><<<g2, 512, SMEM_GEMM>>>(outp);

    long long extra = (long long)out_size - OUT_ELEMS;
    long long work = T_TOKENS + (extra > 0 ? extra : 0);
    unsigned nb = (unsigned)((work + 255) / 256);
    finish_kernel<<<nb, 256>>>(outp, (long long)out_size);
}